// round 17
// baseline (speedup 1.0000x reference)
#include <cuda_runtime.h>
#include <cuda_bf16.h>
#include <cuda_fp16.h>
#include <cstdint>

#define D128 128
#define MAXN 50000
#define MAXE 800000
#define WSTR 68               // padded word stride (64 k-pair words + 4 pad)
#define SCAN_TPB 256

// ---------------- scratch ----------------
__device__ uint32_t g_H16[MAXN * 64];   // H rows as 64 half2 words
__device__ uint32_t g_O16[MAXN * 64];   // layer-1 output rows as 64 half2 words
__device__ int      g_deg[MAXN];        // real in-degree (no self loop)
__device__ float    g_dinv[MAXN];       // rsqrt(deg+1)
__device__ int      g_rowstart[MAXN];
__device__ int      g_cursor[MAXN];
__device__ int      g_csrc[MAXE];
__device__ int      g_blocksum[SCAN_TPB];
__device__ float    g_sum[D128];
__device__ float    g_sumsq[D128];
__device__ uint32_t g_Wth[2 * 128 * 64];  // W^T hi bf16 k-pair packed [slot][n][p]
__device__ uint32_t g_Wtl[2 * 128 * 64];  // W^T lo

__device__ __forceinline__ uint32_t pack_bf16(float f0, float f1) {
    __nv_bfloat162 h = __floats2bfloat162_rn(f0, f1);
    return *reinterpret_cast<uint32_t*>(&h);
}
__device__ __forceinline__ uint32_t pack_h16(float f0, float f1) {
    __half2 h = __floats2half2_rn(f0, f1);
    return *reinterpret_cast<uint32_t*>(&h);
}

// ---------------- setup: zero deg + BN sums, split both W ----------------
__global__ void k_setup(int N, const float* __restrict__ W1, const float* __restrict__ W2) {
    int idx = blockIdx.x * blockDim.x + threadIdx.x;
    if (idx < N) g_deg[idx] = 0;
    if (idx < D128) { g_sum[idx] = 0.f; g_sumsq[idx] = 0.f; }
    if (idx < 2 * 128 * 64) {
        int slot = idx >> 13;
        int loc  = idx & 8191;
        int n = loc >> 6, p = loc & 63;
        const float* W = slot ? W2 : W1;
        float w0 = W[(2 * p) * D128 + n];
        float w1 = W[(2 * p + 1) * D128 + n];
        __nv_bfloat16 h0 = __float2bfloat16_rn(w0);
        __nv_bfloat16 h1 = __float2bfloat16_rn(w1);
        g_Wth[idx] = pack_bf16(__bfloat162float(h0), __bfloat162float(h1));
        g_Wtl[idx] = pack_bf16(w0 - __bfloat162float(h0), w1 - __bfloat162float(h1));
    }
}

// ---------------- degree (4 edges/thread, int4) ----------------
__global__ void k_deg(const int* __restrict__ dst, int E) {
    int e4 = (blockIdx.x * blockDim.x + threadIdx.x) * 4;
    if (e4 + 3 < E) {
        int4 d = *(const int4*)(dst + e4);
        atomicAdd(&g_deg[d.x], 1);
        atomicAdd(&g_deg[d.y], 1);
        atomicAdd(&g_deg[d.z], 1);
        atomicAdd(&g_deg[d.w], 1);
    } else {
        for (int e = e4; e < E; e++) atomicAdd(&g_deg[dst[e]], 1);
    }
}

// ---------------- scan of deg (2 kernels; scan3 self-computes block offset) ----------------
__global__ void k_scan1(int N) {
    __shared__ int sh[SCAN_TPB];
    int t = threadIdx.x;
    int i = blockIdx.x * SCAN_TPB + t;
    int v = (i < N) ? g_deg[i] : 0;
    if (i < N) g_dinv[i] = rsqrtf((float)(v + 1));
    sh[t] = v;
    __syncthreads();
    #pragma unroll
    for (int off = 1; off < SCAN_TPB; off <<= 1) {
        int add = (t >= off) ? sh[t - off] : 0;
        __syncthreads();
        sh[t] += add;
        __syncthreads();
    }
    if (i < N) g_rowstart[i] = sh[t] - v;
    if (t == SCAN_TPB - 1) g_blocksum[blockIdx.x] = sh[t];
}
__global__ void k_scan3(int N) {
    __shared__ int sh[SCAN_TPB];
    int t = threadIdx.x;
    int partial = 0;
    for (int i = t; i < (int)blockIdx.x; i += SCAN_TPB) partial += g_blocksum[i];
    sh[t] = partial;
    __syncthreads();
    #pragma unroll
    for (int off = SCAN_TPB / 2; off > 0; off >>= 1) {
        if (t < off) sh[t] += sh[t + off];
        __syncthreads();
    }
    int base = sh[0];
    int i = blockIdx.x * SCAN_TPB + t;
    if (i < N) {
        int rs = g_rowstart[i] + base;
        g_rowstart[i] = rs;
        g_cursor[i]   = rs;
    }
}

// ---------------- CSR fill (8 edges/thread, 2x int4) ----------------
__global__ void k_fill(const int* __restrict__ src, const int* __restrict__ dst, int E) {
    int e8 = (blockIdx.x * blockDim.x + threadIdx.x) * 8;
    if (e8 + 7 < E) {
        int4 d0 = *(const int4*)(dst + e8);
        int4 d1 = *(const int4*)(dst + e8 + 4);
        int4 s0 = *(const int4*)(src + e8);
        int4 s1 = *(const int4*)(src + e8 + 4);
        g_csrc[atomicAdd(&g_cursor[d0.x], 1)] = s0.x;
        g_csrc[atomicAdd(&g_cursor[d0.y], 1)] = s0.y;
        g_csrc[atomicAdd(&g_cursor[d0.z], 1)] = s0.z;
        g_csrc[atomicAdd(&g_cursor[d0.w], 1)] = s0.w;
        g_csrc[atomicAdd(&g_cursor[d1.x], 1)] = s1.x;
        g_csrc[atomicAdd(&g_cursor[d1.y], 1)] = s1.y;
        g_csrc[atomicAdd(&g_cursor[d1.z], 1)] = s1.z;
        g_csrc[atomicAdd(&g_cursor[d1.w], 1)] = s1.w;
    } else {
        for (int e = e8; e < E; e++)
            g_csrc[atomicAdd(&g_cursor[dst[e]], 1)] = src[e];
    }
}

// ---------------- tensor-core GEMM (writes H16; optional fp16 A + in-kernel BN) ----------------
#define MMA3(accp, a0,a1,a2,a3, b0,b1) \
    asm volatile("mma.sync.aligned.m16n8k16.row.col.f32.bf16.bf16.f32 " \
        "{%0,%1,%2,%3}, {%4,%5,%6,%7}, {%8,%9}, {%0,%1,%2,%3};" \
        : "+f"((accp)[0]), "+f"((accp)[1]), "+f"((accp)[2]), "+f"((accp)[3]) \
        : "r"(a0), "r"(a1), "r"(a2), "r"(a3), "r"(b0), "r"(b1))

__global__ __launch_bounds__(128) void k_gemm_tc(
    const float* __restrict__ A,        // fp32 input (layer 1) or null
    int use_a16,                        // layer 2: read g_O16
    int N, int wslot,
    const float* __restrict__ gamma, const float* __restrict__ beta)
{
    extern __shared__ uint32_t sm[];
    uint32_t* WH = sm;                 // [128][WSTR]
    uint32_t* WL = sm + 128 * WSTR;
    uint32_t* AH = sm + 256 * WSTR;    // [64][WSTR]
    uint32_t* AL = sm + 256 * WSTR + 64 * WSTR;
    float*    BNs = (float*)(sm + 384 * WSTR);   // [128]
    float*    BNb = BNs + 128;                   // [128]

    const int tid  = threadIdx.x;
    const int brow = blockIdx.x * 64;
    const bool do_bn = (gamma != nullptr);

    if (do_bn) {
        float inv_n = 1.0f / (float)N;
        float mu  = g_sum[tid] * inv_n;
        float var = g_sumsq[tid] * inv_n - mu * mu;
        float rstd = rsqrtf(var + 1e-5f);
        float s = rstd * gamma[tid];
        BNs[tid] = s;
        BNb[tid] = beta[tid] - mu * s;
    }

    {
        const uint4* Wg  = (const uint4*)(g_Wth + wslot * 8192);
        const uint4* Wg2 = (const uint4*)(g_Wtl + wslot * 8192);
        #pragma unroll
        for (int i = 0; i < 16; i++) {
            int v = tid + i * 128;
            int w = v * 4;
            int r = w >> 6, c = w & 63;
            uint4 q = Wg[v];
            uint32_t* p = WH + r * WSTR + c;
            p[0] = q.x; p[1] = q.y; p[2] = q.z; p[3] = q.w;
            uint4 q2 = Wg2[v];
            uint32_t* p2 = WL + r * WSTR + c;
            p2[0] = q2.x; p2[1] = q2.y; p2[2] = q2.z; p2[3] = q2.w;
        }
    }
    __syncthreads();   // BN coefs + W visible

    #pragma unroll
    for (int i = 0; i < 16; i++) {
        int v = tid + i * 128;
        int r = v >> 5, c4 = v & 31;
        int grow = brow + r;
        float4 x = make_float4(0.f, 0.f, 0.f, 0.f);
        if (grow < N) {
            if (use_a16) {
                uint2 h = ((const uint2*)(g_O16 + (size_t)grow * 64))[c4];
                float2 a = __half22float2(*reinterpret_cast<__half2*>(&h.x));
                float2 b = __half22float2(*reinterpret_cast<__half2*>(&h.y));
                x = make_float4(a.x, a.y, b.x, b.y);
            } else {
                x = ((const float4*)(A + (size_t)grow * D128))[c4];
            }
        }
        if (do_bn) {
            int f = c4 * 4;
            x.x = fmaxf(fmaf(x.x, BNs[f + 0], BNb[f + 0]), 0.f);
            x.y = fmaxf(fmaf(x.y, BNs[f + 1], BNb[f + 1]), 0.f);
            x.z = fmaxf(fmaf(x.z, BNs[f + 2], BNb[f + 2]), 0.f);
            x.w = fmaxf(fmaf(x.w, BNs[f + 3], BNb[f + 3]), 0.f);
        }
        __nv_bfloat16 hx = __float2bfloat16_rn(x.x);
        __nv_bfloat16 hy = __float2bfloat16_rn(x.y);
        __nv_bfloat16 hz = __float2bfloat16_rn(x.z);
        __nv_bfloat16 hw = __float2bfloat16_rn(x.w);
        int base = r * WSTR + 2 * c4;
        AH[base]     = pack_bf16(__bfloat162float(hx), __bfloat162float(hy));
        AH[base + 1] = pack_bf16(__bfloat162float(hz), __bfloat162float(hw));
        AL[base]     = pack_bf16(x.x - __bfloat162float(hx), x.y - __bfloat162float(hy));
        AL[base + 1] = pack_bf16(x.z - __bfloat162float(hz), x.w - __bfloat162float(hw));
    }
    __syncthreads();

    const int lane = tid & 31, warp = tid >> 5;
    const int g = lane >> 2, t = lane & 3;
    const int wrow = warp * 16;

    float acc[16][4];
    #pragma unroll
    for (int nt = 0; nt < 16; nt++)
        #pragma unroll
        for (int j = 0; j < 4; j++) acc[nt][j] = 0.f;

    #pragma unroll
    for (int ks = 0; ks < 8; ks++) {
        const int kp = ks * 8;
        uint32_t ah0 = AH[(wrow + g)     * WSTR + kp + t];
        uint32_t ah1 = AH[(wrow + g + 8) * WSTR + kp + t];
        uint32_t ah2 = AH[(wrow + g)     * WSTR + kp + t + 4];
        uint32_t ah3 = AH[(wrow + g + 8) * WSTR + kp + t + 4];
        uint32_t al0 = AL[(wrow + g)     * WSTR + kp + t];
        uint32_t al1 = AL[(wrow + g + 8) * WSTR + kp + t];
        uint32_t al2 = AL[(wrow + g)     * WSTR + kp + t + 4];
        uint32_t al3 = AL[(wrow + g + 8) * WSTR + kp + t + 4];
        #pragma unroll
        for (int nt = 0; nt < 16; nt++) {
            int n = nt * 8 + g;
            uint32_t bh0 = WH[n * WSTR + kp + t];
            uint32_t bh1 = WH[n * WSTR + kp + t + 4];
            uint32_t bl0 = WL[n * WSTR + kp + t];
            uint32_t bl1 = WL[n * WSTR + kp + t + 4];
            MMA3(acc[nt], ah0, ah1, ah2, ah3, bh0, bh1);
            MMA3(acc[nt], ah0, ah1, ah2, ah3, bl0, bl1);
            MMA3(acc[nt], al0, al1, al2, al3, bh0, bh1);
        }
    }

    const int r0 = brow + wrow + g;
    const int r1 = r0 + 8;
    #pragma unroll
    for (int nt = 0; nt < 16; nt++) {
        int wcol = nt * 4 + t;
        if (r0 < N) g_H16[(size_t)r0 * 64 + wcol] = pack_h16(acc[nt][0], acc[nt][1]);
        if (r1 < N) g_H16[(size_t)r1 * 64 + wcol] = pack_h16(acc[nt][2], acc[nt][3]);
    }
}

// ---------------- CSR gather aggregation (fp16 gathers; fp16 or fp32 out) ----------------
__device__ __forceinline__ float4 ld_h16(int row, int lane) {
    uint2 v = ((const uint2*)(g_H16 + (size_t)row * 64))[lane];
    float2 a = __half22float2(*reinterpret_cast<__half2*>(&v.x));
    float2 b = __half22float2(*reinterpret_cast<__half2*>(&v.y));
    return make_float4(a.x, a.y, b.x, b.y);
}

template <bool OUT16>
__global__ __launch_bounds__(256) void k_agg(
    float* __restrict__ O, const float* __restrict__ bias, int N)
{
    int node = (blockIdx.x * blockDim.x + threadIdx.x) >> 5;
    int lane = threadIdx.x & 31;
    if (node >= N) return;

    float di = g_dinv[node];
    float w  = di * di;
    float4 h = ld_h16(node, lane);
    float4 acc;
    acc.x = h.x * w; acc.y = h.y * w; acc.z = h.z * w; acc.w = h.w * w;

    const int start = g_rowstart[node];
    const int cnt   = g_deg[node];
    const int* __restrict__ cs = g_csrc + start;

    int j = 0;
    for (; j + 2 <= cnt; j += 2) {
        int s0 = cs[j];
        int s1 = cs[j + 1];
        float n0 = g_dinv[s0] * di;
        float n1 = g_dinv[s1] * di;
        float4 v0 = ld_h16(s0, lane);
        float4 v1 = ld_h16(s1, lane);
        acc.x = fmaf(v0.x, n0, acc.x); acc.y = fmaf(v0.y, n0, acc.y);
        acc.z = fmaf(v0.z, n0, acc.z); acc.w = fmaf(v0.w, n0, acc.w);
        acc.x = fmaf(v1.x, n1, acc.x); acc.y = fmaf(v1.y, n1, acc.y);
        acc.z = fmaf(v1.z, n1, acc.z); acc.w = fmaf(v1.w, n1, acc.w);
    }
    if (j < cnt) {
        int s0 = cs[j];
        float n0 = g_dinv[s0] * di;
        float4 v0 = ld_h16(s0, lane);
        acc.x = fmaf(v0.x, n0, acc.x); acc.y = fmaf(v0.y, n0, acc.y);
        acc.z = fmaf(v0.z, n0, acc.z); acc.w = fmaf(v0.w, n0, acc.w);
    }

    float4 bb = ((const float4*)bias)[lane];
    acc.x += bb.x; acc.y += bb.y; acc.z += bb.z; acc.w += bb.w;

    if (OUT16) {
        uint2 o;
        o.x = pack_h16(acc.x, acc.y);
        o.y = pack_h16(acc.z, acc.w);
        ((uint2*)(g_O16 + (size_t)node * 64))[lane] = o;
    } else {
        ((float4*)(O + (size_t)node * D128))[lane] = acc;
    }
}

// ---------------- BatchNorm stats from fp16 O1 ----------------
__global__ __launch_bounds__(256) void k_bnreduce16(int N) {
    int w  = threadIdx.x & 63;     // half2 word (features 2w, 2w+1)
    int rh = threadIdx.x >> 6;     // 0..3 row phase
    float s0 = 0.f, s1 = 0.f, q0 = 0.f, q1 = 0.f;
    for (int row = blockIdx.x * 4 + rh; row < N; row += gridDim.x * 4) {
        uint32_t v = g_O16[(size_t)row * 64 + w];
        float2 f = __half22float2(*reinterpret_cast<__half2*>(&v));
        s0 += f.x; q0 = fmaf(f.x, f.x, q0);
        s1 += f.y; q1 = fmaf(f.y, f.y, q1);
    }
    __shared__ float shs0[256], shs1[256], shq0[256], shq1[256];
    shs0[threadIdx.x] = s0; shs1[threadIdx.x] = s1;
    shq0[threadIdx.x] = q0; shq1[threadIdx.x] = q1;
    __syncthreads();
    if (threadIdx.x < 64) {
        float ts0 = shs0[w] + shs0[w + 64] + shs0[w + 128] + shs0[w + 192];
        float ts1 = shs1[w] + shs1[w + 64] + shs1[w + 128] + shs1[w + 192];
        float tq0 = shq0[w] + shq0[w + 64] + shq0[w + 128] + shq0[w + 192];
        float tq1 = shq1[w] + shq1[w + 64] + shq1[w + 128] + shq1[w + 192];
        atomicAdd(&g_sum[2 * w],     ts0);
        atomicAdd(&g_sum[2 * w + 1], ts1);
        atomicAdd(&g_sumsq[2 * w],     tq0);
        atomicAdd(&g_sumsq[2 * w + 1], tq1);
    }
}

// ---------------- launch ----------------
extern "C" void kernel_launch(void* const* d_in, const int* in_sizes, int n_in,
                              void* d_out, int out_size)
{
    const float* x     = (const float*)d_in[0];
    const int*   eidx  = (const int*)d_in[1];
    const float* W1    = (const float*)d_in[2];
    const float* b1    = (const float*)d_in[3];
    const float* gamma = (const float*)d_in[4];
    const float* beta  = (const float*)d_in[5];
    const float* W2    = (const float*)d_in[6];
    const float* b2    = (const float*)d_in[7];
    float*       out   = (float*)d_out;

    const int N = in_sizes[0] / D128;          // 50000
    const int E = in_sizes[1] / 2;             // 800000
    const int* src = eidx;
    const int* dst = eidx + E;

    const int GEMM_SMEM = (384 * WSTR + 256) * 4;   // 105472 B
    cudaFuncSetAttribute(k_gemm_tc, cudaFuncAttributeMaxDynamicSharedMemorySize, GEMM_SMEM);

    const int TPB = 256;
    int gridN  = (N + TPB - 1) / TPB;
    int gridE4 = ((E + 3) / 4 + TPB - 1) / TPB;
    int gridE8 = ((E + 7) / 8 + TPB - 1) / TPB;
    int gridG  = (N + 63) / 64;
    int gridA  = (N * 32 + TPB - 1) / TPB;     // warp per node
    int nscan  = (N + SCAN_TPB - 1) / SCAN_TPB;

    // graph structure (per call, deterministic)
    k_setup<<<gridN, TPB>>>(N, W1, W2);
    k_deg<<<gridE4, TPB>>>(dst, E);
    k_scan1<<<nscan, SCAN_TPB>>>(N);
    k_scan3<<<nscan, SCAN_TPB>>>(N);
    k_fill<<<gridE8, TPB>>>(src, dst, E);

    // layer 1 (O1 stored fp16)
    k_gemm_tc<<<gridG, 128, GEMM_SMEM>>>(x, 0, N, 0, nullptr, nullptr);
    k_agg<true><<<gridA, TPB>>>(nullptr, b1, N);

    // batchnorm stats from fp16 O1
    k_bnreduce16<<<256, TPB>>>(N);

    // layer 2 (fp16 A-read, BN coef in-kernel, BN+ReLU fused; fp32 out)
    k_gemm_tc<<<gridG, 128, GEMM_SMEM>>>(nullptr, 1, N, 1, gamma, beta);
    k_agg<false><<<gridA, TPB>>>(out, b2, N);
}